// round 1
// baseline (speedup 1.0000x reference)
#include <cuda_runtime.h>

// Conv2d 3x3 as implicit GEMM, fp32 SIMT baseline.
// GEMM: C[M=256][N=100352] = A[M][K=1152] * B[K][N]
//   A[co][k]   = w viewed as 256x1152 row-major (k = ci*9 + kh*3 + kw)
//   B[k][n]    = x[b, ci, oh+kh-1, ow+kw-1]  (n = b*3136 + oh*56 + ow), 0 if OOB
// Tiling: 128x128 block tile, K-tile 8, 256 threads, 8x8 per-thread micro-tile,
// double-buffered smem (1 barrier per K step).

namespace {
constexpr int BATCH = 32;
constexpr int CIN   = 128;
constexpr int HH    = 56;
constexpr int WW    = 56;
constexpr int COUT  = 256;
constexpr int HW    = HH * WW;          // 3136
constexpr int KDIM  = CIN * 9;          // 1152
constexpr int NDIM  = BATCH * HW;       // 100352

constexpr int TM = 128;
constexpr int TN = 128;
constexpr int TK = 8;
constexpr int NKT = KDIM / TK;          // 144
constexpr int TM_PAD = TM + 4;          // avoid STS bank conflicts on A transpose
}

__device__ __forceinline__ float gather_b(const float* __restrict__ x,
                                          int k, int bb, int oh, int ow) {
    int ci = k / 9;
    int r  = k - ci * 9;
    int kh = r / 3;
    int kw = r - kh * 3;
    int ih = oh + kh - 1;
    int iw = ow + kw - 1;
    if ((unsigned)ih < (unsigned)HH && (unsigned)iw < (unsigned)WW) {
        return __ldg(&x[((bb * CIN + ci) * HH + ih) * WW + iw]);
    }
    return 0.0f;
}

__global__ __launch_bounds__(256, 2)
void conv_igemm_kernel(const float* __restrict__ x,
                       const float* __restrict__ w,
                       const float* __restrict__ bias,
                       float* __restrict__ out)
{
    __shared__ float As[2][TK][TM_PAD];   // k-major A tile (transposed on store)
    __shared__ float Bs[2][TK][TN];       // k-major B tile

    const int tid = threadIdx.x;
    const int bn  = blockIdx.x;           // 0..783  (N tiles)
    const int bm  = blockIdx.y;           // 0..1    (M tiles)

    // micro-tile coordinates: 16x16 thread grid, each does 8(M) x 8(N)
    const int tm = tid >> 4;              // 0..15
    const int tn = tid & 15;              // 0..15

    // ---- A load assignment: row = tid/2 (0..127), k-offset = (tid&1)*4, float4
    const int a_row  = tid >> 1;
    const int a_kcol = (tid & 1) * 4;
    const float* wptr = w + (size_t)(bm * TM + a_row) * KDIM + a_kcol;

    // ---- B load assignment: k-row = tid/32 (0..7), 4 consecutive n columns
    const int b_krow = tid >> 5;
    const int b_col0 = (tid & 31) * 4;

    int bb[4], ohh[4], oww[4];
#pragma unroll
    for (int i = 0; i < 4; ++i) {
        int n   = bn * TN + b_col0 + i;
        bb[i]   = n / HW;
        int rem = n - bb[i] * HW;
        ohh[i]  = rem / WW;
        oww[i]  = rem - ohh[i] * WW;
    }

    // ---- prologue: load K-step 0 into buffer 0
    {
        float4 a0 = *reinterpret_cast<const float4*>(wptr);
        As[0][a_kcol + 0][a_row] = a0.x;
        As[0][a_kcol + 1][a_row] = a0.y;
        As[0][a_kcol + 2][a_row] = a0.z;
        As[0][a_kcol + 3][a_row] = a0.w;

        int k = b_krow;  // kt = 0
        float4 bv;
        bv.x = gather_b(x, k, bb[0], ohh[0], oww[0]);
        bv.y = gather_b(x, k, bb[1], ohh[1], oww[1]);
        bv.z = gather_b(x, k, bb[2], ohh[2], oww[2]);
        bv.w = gather_b(x, k, bb[3], ohh[3], oww[3]);
        *reinterpret_cast<float4*>(&Bs[0][b_krow][b_col0]) = bv;
    }
    __syncthreads();

    float acc[8][8];
#pragma unroll
    for (int i = 0; i < 8; ++i)
#pragma unroll
        for (int j = 0; j < 8; ++j) acc[i][j] = 0.0f;

    // ---- main K loop, double buffered
    for (int kt = 0; kt < NKT; ++kt) {
        const int cur = kt & 1;

        // prefetch next K-step into registers
        float4 aPre;
        float4 bPre;
        const bool has_next = (kt + 1 < NKT);
        if (has_next) {
            aPre = *reinterpret_cast<const float4*>(wptr + (kt + 1) * TK);
            int k = (kt + 1) * TK + b_krow;
            bPre.x = gather_b(x, k, bb[0], ohh[0], oww[0]);
            bPre.y = gather_b(x, k, bb[1], ohh[1], oww[1]);
            bPre.z = gather_b(x, k, bb[2], ohh[2], oww[2]);
            bPre.w = gather_b(x, k, bb[3], ohh[3], oww[3]);
        }

        // compute on current buffer
#pragma unroll
        for (int kk = 0; kk < TK; ++kk) {
            float4 a0 = *reinterpret_cast<const float4*>(&As[cur][kk][tm * 8]);
            float4 a1 = *reinterpret_cast<const float4*>(&As[cur][kk][tm * 8 + 4]);
            float4 b0 = *reinterpret_cast<const float4*>(&Bs[cur][kk][tn * 8]);
            float4 b1 = *reinterpret_cast<const float4*>(&Bs[cur][kk][tn * 8 + 4]);
            float av[8] = {a0.x, a0.y, a0.z, a0.w, a1.x, a1.y, a1.z, a1.w};
            float bv[8] = {b0.x, b0.y, b0.z, b0.w, b1.x, b1.y, b1.z, b1.w};
#pragma unroll
            for (int i = 0; i < 8; ++i)
#pragma unroll
                for (int j = 0; j < 8; ++j)
                    acc[i][j] = fmaf(av[i], bv[j], acc[i][j]);
        }

        if (has_next) {
            const int nxt = cur ^ 1;
            As[nxt][a_kcol + 0][a_row] = aPre.x;
            As[nxt][a_kcol + 1][a_row] = aPre.y;
            As[nxt][a_kcol + 2][a_row] = aPre.z;
            As[nxt][a_kcol + 3][a_row] = aPre.w;
            *reinterpret_cast<float4*>(&Bs[nxt][b_krow][b_col0]) = bPre;
            __syncthreads();
        }
    }

    // ---- epilogue: add bias, scatter to NCHW output
    int obase[8];
#pragma unroll
    for (int j = 0; j < 8; ++j) {
        int n   = bn * TN + tn * 8 + j;
        int nb  = n / HW;
        int rem = n - nb * HW;
        obase[j] = nb * COUT * HW + rem;
    }
#pragma unroll
    for (int i = 0; i < 8; ++i) {
        int co = bm * TM + tm * 8 + i;
        float bi = __ldg(&bias[co]);
        int coff = co * HW;
#pragma unroll
        for (int j = 0; j < 8; ++j) {
            out[obase[j] + coff] = acc[i][j] + bi;
        }
    }
}

extern "C" void kernel_launch(void* const* d_in, const int* in_sizes, int n_in,
                              void* d_out, int out_size) {
    const float* x    = (const float*)d_in[0];  // [32,128,56,56]
    const float* w    = (const float*)d_in[1];  // [256,128,3,3]
    const float* bias = (const float*)d_in[2];  // [256]
    float* out        = (float*)d_out;          // [32,256,56,56]

    dim3 grid(NDIM / TN, COUT / TM);  // (784, 2)
    dim3 block(256);
    conv_igemm_kernel<<<grid, block>>>(x, w, bias, out);
}

// round 3
// speedup vs baseline: 1.1673x; 1.1673x over previous
#include <cuda_runtime.h>
#include <cstdint>

// Conv2d 3x3 (B=32,Cin=128,56x56 -> Cout=256, pad 1) as implicit GEMM using
// mma.sync.m16n8k8 tf32 tensor cores (arch-agnostic PTX; compute_103-safe).
//
// GEMM: D[M=256][N=100352] = A[M][K=1152] * B[K][N]
//   A[co][k] = w viewed as 256x1152 row-major (k = ci*9 + kh*3 + kw)
//   B[k][n]  = x[b, ci, oh+kh-1, ow+kw-1]  (im2col gather, 0 on padding)
// Single-pass tf32 (rel err ~3e-4 < 1e-3 gate).

namespace {
constexpr int HH = 56, WW = 56, HW = 3136;
constexpr int CIN = 128, COUT = 256;
constexpr int KDIM = CIN * 9;          // 1152
constexpr int NDIM = 32 * HW;          // 100352
constexpr int TM = 128, TN = 128, KT = 32;
constexpr int NKT = KDIM / KT;         // 36

constexpr int LD   = TM + 4;           // padded row length (floats)
constexpr int STG  = KT * LD;          // floats per stage tile = 4224
// dynamic smem: A[2 stages] then B[2 stages]
constexpr uint32_t SMEM_TOTAL = 4u * STG * sizeof(float);  // 67584 B
}

__device__ __forceinline__ uint32_t f2tf32(float v) {
    uint32_t u;
    asm("cvt.rna.tf32.f32 %0, %1;" : "=r"(u) : "f"(v));
    return u;
}

__device__ __forceinline__ void mma_tf32(float* d, const uint32_t* a, const uint32_t* b) {
    asm volatile(
        "mma.sync.aligned.m16n8k8.row.col.f32.tf32.tf32.f32 "
        "{%0,%1,%2,%3}, {%4,%5,%6,%7}, {%8,%9}, {%0,%1,%2,%3};"
        : "+f"(d[0]), "+f"(d[1]), "+f"(d[2]), "+f"(d[3])
        : "r"(a[0]), "r"(a[1]), "r"(a[2]), "r"(a[3]), "r"(b[0]), "r"(b[1]));
}

__global__ __launch_bounds__(256)
void conv_mma_kernel(const float* __restrict__ x, const float* __restrict__ w,
                     const float* __restrict__ bias, float* __restrict__ out)
{
    extern __shared__ float sm[];
    float* Abuf = sm;            // [2][KT][LD]
    float* Bbuf = sm + 2 * STG;  // [2][KT][LD]

    const int tid  = threadIdx.x;
    const int lane = tid & 31;
    const int wid  = tid >> 5;
    const int bn   = blockIdx.x;     // N tile 0..783
    const int bm   = blockIdx.y;     // M tile 0..1

    // ---- per-thread fill assignment: 16 k-elements of one tile row ----
    const int row = tid >> 1;             // 0..127 (co-row for A, n-col for B)
    const int ks  = (tid & 1) * 16;       // local k offset

    const float* wrow = w + (size_t)(bm * TM + row) * KDIM + ks;

    const int nglob = bn * TN + row;
    const int bb  = nglob / HW;
    const int rem = nglob - bb * HW;
    const int oh  = rem / WW;
    const int ow  = rem - oh * WW;
    const float* xb = x + (size_t)bb * (CIN * HW) + (oh - 1) * WW + (ow - 1);
    const bool vh0 = (oh >= 1), vh2 = (oh < HH - 1);
    const bool vw0 = (ow >= 1), vw2 = (ow < WW - 1);

    // k = kt*32 + ks + e ; decomposed state (ci0, r0) for e=0
    int ci0 = (tid & 1) ? 1 : 0;
    int r0  = (tid & 1) ? 7 : 0;

    auto fill = [&](int stage, const float* wp, int ci0_, int r0_) {
        float* As = Abuf + stage * STG;
        float* Bs = Bbuf + stage * STG;
        // A: 16 consecutive k values (4x float4), convert to tf32, k-major STS
#pragma unroll
        for (int jj = 0; jj < 4; ++jj) {
            float4 v = *reinterpret_cast<const float4*>(wp + 4 * jj);
            As[(ks + 4 * jj + 0) * LD + row] = __uint_as_float(f2tf32(v.x));
            As[(ks + 4 * jj + 1) * LD + row] = __uint_as_float(f2tf32(v.y));
            As[(ks + 4 * jj + 2) * LD + row] = __uint_as_float(f2tf32(v.z));
            As[(ks + 4 * jj + 3) * LD + row] = __uint_as_float(f2tf32(v.w));
        }
        // B: im2col gather of 16 k values for this n-column
#pragma unroll
        for (int e = 0; e < 16; ++e) {
            int r = r0_ + e;
            int add = (r >= 9) + (r >= 18);
            int ci  = ci0_ + add;
            int rr  = r - 9 * add;
            int kh  = (rr >= 3) + (rr >= 6);
            int kw  = rr - 3 * kh;
            bool okh = (kh == 1) || (kh == 0 ? vh0 : vh2);
            bool okw = (kw == 1) || (kw == 0 ? vw0 : vw2);
            float v = (okh && okw) ? __ldg(xb + ci * HW + kh * WW + kw) : 0.0f;
            Bs[(ks + e) * LD + row] = __uint_as_float(f2tf32(v));
        }
    };

    // ---- warp/lane compute coordinates ----
    const int wm = wid >> 1;         // 0..3 -> 32 M rows
    const int wn = wid & 1;          // 0..1 -> 64 N cols
    const int gr = lane >> 2;        // 0..7
    const int qc = lane & 3;         // 0..3
    const int mb = wm * 32;
    const int nb = wn * 64;

    float acc[2][8][4];
#pragma unroll
    for (int i = 0; i < 2; ++i)
#pragma unroll
        for (int j = 0; j < 8; ++j)
#pragma unroll
            for (int q = 0; q < 4; ++q) acc[i][j][q] = 0.0f;

    // ---- prologue ----
    fill(0, wrow, ci0, r0);
    __syncthreads();

    // ---- main loop: fill(next) then compute(cur), one sync per K-step ----
    for (int kt = 0; kt < NKT; ++kt) {
        const int cur = kt & 1;
        if (kt + 1 < NKT) {
            r0 += 5; ci0 += 3;
            if (r0 >= 9) { r0 -= 9; ci0 += 1; }
            fill(cur ^ 1, wrow + (size_t)(kt + 1) * KT, ci0, r0);
        }

        const float* Ac = Abuf + cur * STG;
        const float* Bc = Bbuf + cur * STG;
#pragma unroll
        for (int s = 0; s < 4; ++s) {
            const int k0 = s * 8;
            const float* Ak0 = Ac + (k0 + qc) * LD;
            const float* Ak4 = Ac + (k0 + qc + 4) * LD;
            const float* Bk0 = Bc + (k0 + qc) * LD;
            const float* Bk4 = Bc + (k0 + qc + 4) * LD;

            uint32_t afr[2][4];
#pragma unroll
            for (int i = 0; i < 2; ++i) {
                int m0 = mb + i * 16 + gr;
                afr[i][0] = __float_as_uint(Ak0[m0]);
                afr[i][1] = __float_as_uint(Ak0[m0 + 8]);
                afr[i][2] = __float_as_uint(Ak4[m0]);
                afr[i][3] = __float_as_uint(Ak4[m0 + 8]);
            }
            uint32_t bfr[8][2];
#pragma unroll
            for (int j = 0; j < 8; ++j) {
                int n0 = nb + j * 8 + gr;
                bfr[j][0] = __float_as_uint(Bk0[n0]);
                bfr[j][1] = __float_as_uint(Bk4[n0]);
            }
#pragma unroll
            for (int i = 0; i < 2; ++i)
#pragma unroll
                for (int j = 0; j < 8; ++j)
                    mma_tf32(acc[i][j], afr[i], bfr[j]);
        }
        __syncthreads();
    }

    // ---- epilogue: bias + direct float2 stores (32B-sector coalesced) ----
#pragma unroll
    for (int i = 0; i < 2; ++i) {
        const int co0 = bm * TM + mb + i * 16 + gr;
        const int co1 = co0 + 8;
        const float bi0 = __ldg(&bias[co0]);
        const float bi1 = __ldg(&bias[co1]);
#pragma unroll
        for (int j = 0; j < 8; ++j) {
            const int n0  = bn * TN + nb + j * 8 + 2 * qc;
            const int b2  = n0 / HW;
            const int r2  = n0 - b2 * HW;
            float* obase  = out + (size_t)b2 * (COUT * HW) + r2;
            float2 v0 = make_float2(acc[i][j][0] + bi0, acc[i][j][1] + bi0);
            float2 v1 = make_float2(acc[i][j][2] + bi1, acc[i][j][3] + bi1);
            *reinterpret_cast<float2*>(obase + (size_t)co0 * HW) = v0;
            *reinterpret_cast<float2*>(obase + (size_t)co1 * HW) = v1;
        }
    }
}

extern "C" void kernel_launch(void* const* d_in, const int* in_sizes, int n_in,
                              void* d_out, int out_size) {
    const float* x    = (const float*)d_in[0];  // [32,128,56,56]
    const float* w    = (const float*)d_in[1];  // [256,128,3,3]
    const float* bias = (const float*)d_in[2];  // [256]
    float* out        = (float*)d_out;          // [32,256,56,56]

    cudaFuncSetAttribute(conv_mma_kernel, cudaFuncAttributeMaxDynamicSharedMemorySize,
                         (int)SMEM_TOTAL);
    dim3 grid(NDIM / TN, COUT / TM);  // (784, 2)
    conv_mma_kernel<<<grid, 256, SMEM_TOTAL>>>(x, w, bias, out);
}

// round 5
// speedup vs baseline: 2.7559x; 2.3609x over previous
#include <cuda_runtime.h>
#include <cstdint>

// Conv2d 3x3 (B=32,Cin=128,56x56 -> Cout=256, pad 1) as implicit GEMM using
// mma.sync.m16n8k8 tf32 (arch-agnostic PTX, compute_103-safe).
//
// K reordered position-major: k' = (kh*3+kw)*128 + ci. Each K-tile of 32
// shares one (kh,kw) => B tile is a coalesced 2D copy with one predicate
// per thread. Weights pre-repacked + tf32-pre-rounded into g_wt[k'][co];
// x pre-rounded to tf32 in g_xt. Fill uses cp.async (zfill for padding),
// 3-stage pipeline.

namespace {
constexpr int HH = 56, WW = 56, HW = 3136;
constexpr int CIN = 128, COUT = 256, BATCH = 32;
constexpr int KDIM = CIN * 9;          // 1152
constexpr int NDIM = BATCH * HW;       // 100352
constexpr int TM = 128, TN = 128, KT = 32;
constexpr int NKT = KDIM / KT;         // 36
constexpr int NSTAGE = 3;

constexpr int LD = TM + 4;                       // 132 floats per k-row
constexpr int TILE_FLOATS = KT * LD;             // 4224
constexpr uint32_t STAGE_BYTES = 2u * TILE_FLOATS * 4u;   // A + B = 33792
constexpr uint32_t SMEM_TOTAL = NSTAGE * STAGE_BYTES;     // 101376
}

__device__ float g_xt[(size_t)BATCH * CIN * HW];   // tf32-rounded x
__device__ float g_wt[(size_t)KDIM * COUT];        // repacked tf32 weights [k'][co]

// ---------------- helpers ----------------
__device__ __forceinline__ uint32_t f2tf32(float v) {
    uint32_t u;
    asm("cvt.rna.tf32.f32 %0, %1;" : "=r"(u) : "f"(v));
    return u;
}
__device__ __forceinline__ uint32_t smem_u32(const void* p) {
    uint32_t a;
    asm("{ .reg .u64 t; cvta.to.shared.u64 t, %1; cvt.u32.u64 %0, t; }" : "=r"(a) : "l"(p));
    return a;
}
__device__ __forceinline__ void cp16(uint32_t dst, const float* src) {
    asm volatile("cp.async.cg.shared.global [%0], [%1], 16;"
                 :: "r"(dst), "l"(src) : "memory");
}
__device__ __forceinline__ void cp4z(uint32_t dst, const float* src, uint32_t sz) {
    asm volatile("cp.async.ca.shared.global [%0], [%1], 4, %2;"
                 :: "r"(dst), "l"(src), "r"(sz) : "memory");
}
__device__ __forceinline__ void cp_commit() {
    asm volatile("cp.async.commit_group;" ::: "memory");
}
template <int N>
__device__ __forceinline__ void cp_wait() {
    asm volatile("cp.async.wait_group %0;" :: "n"(N) : "memory");
}
__device__ __forceinline__ void mma_tf32(float* d, const uint32_t* a, const uint32_t* b) {
    asm volatile(
        "mma.sync.aligned.m16n8k8.row.col.f32.tf32.tf32.f32 "
        "{%0,%1,%2,%3}, {%4,%5,%6,%7}, {%8,%9}, {%0,%1,%2,%3};"
        : "+f"(d[0]), "+f"(d[1]), "+f"(d[2]), "+f"(d[3])
        : "r"(a[0]), "r"(a[1]), "r"(a[2]), "r"(a[3]), "r"(b[0]), "r"(b[1]));
}

// ---------------- pre-pass kernels ----------------
__global__ void cvt_x_kernel(const float* __restrict__ x) {
    size_t i = (size_t)blockIdx.x * blockDim.x + threadIdx.x;
    const float4* xin = reinterpret_cast<const float4*>(x);
    float4 v = xin[i];
    float4 o;
    o.x = __uint_as_float(f2tf32(v.x));
    o.y = __uint_as_float(f2tf32(v.y));
    o.z = __uint_as_float(f2tf32(v.z));
    o.w = __uint_as_float(f2tf32(v.w));
    reinterpret_cast<float4*>(g_xt)[i] = o;
}

__global__ void repack_w_kernel(const float* __restrict__ w) {
    int id = blockIdx.x * blockDim.x + threadIdx.x;  // 0 .. KDIM*COUT-1
    int co = id & (COUT - 1);
    int kp = id >> 8;                 // k' = p*128 + ci
    int p  = kp >> 7;
    int ci = kp & 127;
    float v = w[(size_t)co * KDIM + ci * 9 + p];
    g_wt[id] = __uint_as_float(f2tf32(v));
}

// ---------------- main kernel ----------------
__global__ __launch_bounds__(256)
void conv_mma_kernel(const float* __restrict__ bias, float* __restrict__ out)
{
    extern __shared__ float sm[];
    const uint32_t sbase = smem_u32(sm);

    const int tid  = threadIdx.x;
    const int lane = tid & 31;
    const int wid  = tid >> 5;
    const int bn   = blockIdx.x;   // 0..783
    const int bm   = blockIdx.y;   // 0..1

    // ---- A fill assignment: k-row r (0..31), 16 consecutive co ----
    const int a_r  = tid >> 3;
    const int a_c  = (tid & 7) * 16;
    const uint32_t a_dst = sbase + (uint32_t)(a_r * LD + a_c) * 4u;
    const float* a_src0 = g_wt + (size_t)a_r * COUT + bm * TM + a_c;

    // ---- B fill assignment: n column (0..127), 16 ci rows ----
    const int b_n  = tid & 127;
    const int b_r0 = (tid >> 7) * 16;
    const uint32_t b_dst = sbase + (uint32_t)TILE_FLOATS * 4u +
                           (uint32_t)(b_r0 * LD + b_n) * 4u;

    const int nglob = bn * TN + b_n;
    const int bb  = nglob / HW;
    const int rem = nglob - bb * HW;
    const int oh  = rem / WW;
    const int ow  = rem - oh * WW;
    const float* xb = g_xt + (size_t)bb * (CIN * HW) + (oh - 1) * WW + (ow - 1);

    // fill stage s with K-tile kt
    auto fill = [&](int s, int kt) {
        const uint32_t soff = (uint32_t)s * STAGE_BYTES;
        // A: 4 x 16B, always valid
        const float* asrc = a_src0 + (size_t)kt * KT * COUT;
        cp16(a_dst + soff,      asrc);
        cp16(a_dst + soff + 16, asrc + 4);
        cp16(a_dst + soff + 32, asrc + 8);
        cp16(a_dst + soff + 48, asrc + 12);
        // B: one (kh,kw) per K-tile; 16 ci rows, stride HW
        const int p  = kt >> 2;            // 0..8
        const int kh = (p * 11) >> 5;      // p/3 for p<9
        const int kw = p - 3 * kh;
        const int ih = oh + kh - 1;
        const int iw = ow + kw - 1;
        const uint32_t sz = ((unsigned)ih < (unsigned)HH && (unsigned)iw < (unsigned)WW) ? 4u : 0u;
        const int ci0 = ((kt & 3) << 5) + b_r0;
        const float* bsrc = xb + (size_t)ci0 * HW + kh * WW + kw;
#pragma unroll
        for (int e = 0; e < 16; ++e)
            cp4z(b_dst + soff + (uint32_t)(e * LD * 4), bsrc + (size_t)e * HW, sz);
    };

    // ---- warp/lane compute coordinates ----
    const int wm = wid >> 1, wn = wid & 1;
    const int gr = lane >> 2, qc = lane & 3;
    const int mb = wm * 32, nb = wn * 64;

    float acc[2][8][4];
#pragma unroll
    for (int i = 0; i < 2; ++i)
#pragma unroll
        for (int j = 0; j < 8; ++j)
#pragma unroll
            for (int q = 0; q < 4; ++q) acc[i][j][q] = 0.0f;

    // ---- pipeline prologue ----
    fill(0, 0); cp_commit();
    fill(1, 1); cp_commit();

    int stage = 0;
    for (int kt = 0; kt < NKT; ++kt) {
        cp_wait<1>();          // stage (kt%3) ready
        __syncthreads();

        if (kt + 2 < NKT) {
            int s2 = stage + 2; if (s2 >= NSTAGE) s2 -= NSTAGE;
            fill(s2, kt + 2);
        }
        cp_commit();

        const float* Ac = sm + stage * (2 * TILE_FLOATS);
        const float* Bc = Ac + TILE_FLOATS;
#pragma unroll
        for (int s = 0; s < 4; ++s) {
            const int k0 = s * 8;
            const float* Ak0 = Ac + (k0 + qc) * LD;
            const float* Ak4 = Ac + (k0 + qc + 4) * LD;
            const float* Bk0 = Bc + (k0 + qc) * LD;
            const float* Bk4 = Bc + (k0 + qc + 4) * LD;

            uint32_t afr[2][4];
#pragma unroll
            for (int i = 0; i < 2; ++i) {
                int m0 = mb + i * 16 + gr;
                afr[i][0] = __float_as_uint(Ak0[m0]);
                afr[i][1] = __float_as_uint(Ak0[m0 + 8]);
                afr[i][2] = __float_as_uint(Ak4[m0]);
                afr[i][3] = __float_as_uint(Ak4[m0 + 8]);
            }
            uint32_t bfr[8][2];
#pragma unroll
            for (int j = 0; j < 8; ++j) {
                int n0 = nb + j * 8 + gr;
                bfr[j][0] = __float_as_uint(Bk0[n0]);
                bfr[j][1] = __float_as_uint(Bk4[n0]);
            }
#pragma unroll
            for (int i = 0; i < 2; ++i)
#pragma unroll
                for (int j = 0; j < 8; ++j)
                    mma_tf32(acc[i][j], afr[i], bfr[j]);
        }
        __syncthreads();
        if (++stage == NSTAGE) stage = 0;
    }

    // ---- epilogue: bias + float2 stores ----
#pragma unroll
    for (int i = 0; i < 2; ++i) {
        const int co0 = bm * TM + mb + i * 16 + gr;
        const int co1 = co0 + 8;
        const float bi0 = __ldg(&bias[co0]);
        const float bi1 = __ldg(&bias[co1]);
#pragma unroll
        for (int j = 0; j < 8; ++j) {
            const int n0 = bn * TN + nb + j * 8 + 2 * qc;
            const int b2 = n0 / HW;
            const int r2 = n0 - b2 * HW;
            float* obase = out + (size_t)b2 * (COUT * HW) + r2;
            float2 v0 = make_float2(acc[i][j][0] + bi0, acc[i][j][1] + bi0);
            float2 v1 = make_float2(acc[i][j][2] + bi1, acc[i][j][3] + bi1);
            *reinterpret_cast<float2*>(obase + (size_t)co0 * HW) = v0;
            *reinterpret_cast<float2*>(obase + (size_t)co1 * HW) = v1;
        }
    }
}

extern "C" void kernel_launch(void* const* d_in, const int* in_sizes, int n_in,
                              void* d_out, int out_size) {
    const float* x    = (const float*)d_in[0];  // [32,128,56,56]
    const float* w    = (const float*)d_in[1];  // [256,128,3,3]
    const float* bias = (const float*)d_in[2];  // [256]
    float* out        = (float*)d_out;          // [32,256,56,56]

    // pre-passes
    cvt_x_kernel<<<(BATCH * CIN * HW / 4 + 255) / 256, 256>>>(x);
    repack_w_kernel<<<(KDIM * COUT) / 256, 256>>>(w);

    cudaFuncSetAttribute(conv_mma_kernel, cudaFuncAttributeMaxDynamicSharedMemorySize,
                         (int)SMEM_TOTAL);
    dim3 grid(NDIM / TN, COUT / TM);  // (784, 2)
    conv_mma_kernel<<<grid, 256, SMEM_TOTAL>>>(bias, out);
}

// round 7
// speedup vs baseline: 3.6447x; 1.3225x over previous
#include <cuda_runtime.h>
#include <cstdint>

// Conv2d 3x3 (B=32,Cin=128,56x56 -> Cout=256, pad 1) as implicit GEMM using
// mma.sync.m16n8k8 tf32 (arch-agnostic PTX, compute_103-safe).
//
// R6: (a) B smem pad 132->136 dwords: all fragment LDS conflict-free.
//     (b) A operand via ldmatrix.x4: weights repacked per-K-tile in m-major
//         [co][kk] rows of 128B with XOR-16B swizzle pre-applied in gmem;
//         A fill stays 4x cp16/thread, ldmatrix reads conflict-free.

namespace {
constexpr int HH = 56, WW = 56, HW = 3136;
constexpr int CIN = 128, COUT = 256, BATCH = 32;
constexpr int KDIM = CIN * 9;          // 1152
constexpr int NDIM = BATCH * HW;       // 100352
constexpr int TM = 128, TN = 128, KT = 32;
constexpr int NKT = KDIM / KT;         // 36
constexpr int NSTAGE = 3;

constexpr int LDB = TN + 8;                      // 136 dwords per B k-row
constexpr int A_TILE_FLOATS = TM * KT;           // 4096 (m-major, 128B rows)
constexpr int B_TILE_FLOATS = KT * LDB;          // 4352
constexpr uint32_t A_TILE_BYTES = A_TILE_FLOATS * 4u;   // 16384
constexpr uint32_t STAGE_BYTES = (A_TILE_FLOATS + B_TILE_FLOATS) * 4u;  // 33792
constexpr uint32_t SMEM_TOTAL = NSTAGE * STAGE_BYTES;   // 101376
}

__device__ float g_xt[(size_t)BATCH * CIN * HW];   // tf32-rounded x
__device__ float g_wt2[(size_t)KDIM * COUT];       // [kt][co][32 kk, swizzled]

// ---------------- helpers ----------------
__device__ __forceinline__ uint32_t f2tf32(float v) {
    uint32_t u;
    asm("cvt.rna.tf32.f32 %0, %1;" : "=r"(u) : "f"(v));
    return u;
}
__device__ __forceinline__ uint32_t smem_u32(const void* p) {
    uint32_t a;
    asm("{ .reg .u64 t; cvta.to.shared.u64 t, %1; cvt.u32.u64 %0, t; }" : "=r"(a) : "l"(p));
    return a;
}
__device__ __forceinline__ void cp16(uint32_t dst, const float* src) {
    asm volatile("cp.async.cg.shared.global [%0], [%1], 16;"
                 :: "r"(dst), "l"(src) : "memory");
}
__device__ __forceinline__ void cp4z(uint32_t dst, const float* src, uint32_t sz) {
    asm volatile("cp.async.ca.shared.global [%0], [%1], 4, %2;"
                 :: "r"(dst), "l"(src), "r"(sz) : "memory");
}
__device__ __forceinline__ void cp_commit() {
    asm volatile("cp.async.commit_group;" ::: "memory");
}
template <int N>
__device__ __forceinline__ void cp_wait() {
    asm volatile("cp.async.wait_group %0;" :: "n"(N) : "memory");
}
__device__ __forceinline__ void ldsm4(uint32_t* r, uint32_t addr) {
    asm volatile("ldmatrix.sync.aligned.m8n8.x4.shared.b16 {%0,%1,%2,%3}, [%4];"
                 : "=r"(r[0]), "=r"(r[1]), "=r"(r[2]), "=r"(r[3]) : "r"(addr));
}
__device__ __forceinline__ void mma_tf32(float* d, const uint32_t* a, const uint32_t* b) {
    asm volatile(
        "mma.sync.aligned.m16n8k8.row.col.f32.tf32.tf32.f32 "
        "{%0,%1,%2,%3}, {%4,%5,%6,%7}, {%8,%9}, {%0,%1,%2,%3};"
        : "+f"(d[0]), "+f"(d[1]), "+f"(d[2]), "+f"(d[3])
        : "r"(a[0]), "r"(a[1]), "r"(a[2]), "r"(a[3]), "r"(b[0]), "r"(b[1]));
}

// ---------------- pre-pass kernels ----------------
__global__ void cvt_x_kernel(const float* __restrict__ x) {
    size_t i = (size_t)blockIdx.x * blockDim.x + threadIdx.x;
    float4 v = reinterpret_cast<const float4*>(x)[i];
    float4 o;
    o.x = __uint_as_float(f2tf32(v.x));
    o.y = __uint_as_float(f2tf32(v.y));
    o.z = __uint_as_float(f2tf32(v.z));
    o.w = __uint_as_float(f2tf32(v.w));
    reinterpret_cast<float4*>(g_xt)[i] = o;
}

// g_wt2[kt][co][pos] where the 16B group gs=pos>>2 holds true k-group
// g = gs ^ (co&7)  (swizzle pre-applied so ldmatrix rows are conflict-free).
__global__ void repack_w_kernel(const float* __restrict__ w) {
    int id  = blockIdx.x * blockDim.x + threadIdx.x;  // 0..KDIM*COUT-1
    int pos = id & 31;
    int co  = (id >> 5) & 255;
    int kt  = id >> 13;
    int gs  = pos >> 2, e = pos & 3;
    int g   = gs ^ (co & 7);
    int kk  = g * 4 + e;
    int p   = kt >> 2;                    // 0..8  (kh*3+kw)
    int ci  = ((kt & 3) << 5) + kk;       // 0..127
    float v = w[(size_t)co * KDIM + ci * 9 + p];
    g_wt2[id] = __uint_as_float(f2tf32(v));
}

// ---------------- main kernel ----------------
__global__ __launch_bounds__(256, 2)
void conv_mma_kernel(const float* __restrict__ bias, float* __restrict__ out)
{
    extern __shared__ float sm[];
    const uint32_t sbase = smem_u32(sm);

    const int tid  = threadIdx.x;
    const int lane = tid & 31;
    const int wid  = tid >> 5;
    const int bn   = blockIdx.x;   // 0..783
    const int bm   = blockIdx.y;   // 0..1

    // ---- A fill: 64B contiguous per thread from the per-kt blob ----
    const float* a_src0 = g_wt2 + (size_t)bm * (TM * KT) + tid * 16;
    const uint32_t a_dst = sbase + (uint32_t)tid * 64u;

    // ---- B fill: n column (0..127), 16 ci rows ----
    const int b_n  = tid & 127;
    const int b_r0 = (tid >> 7) * 16;
    const uint32_t b_dst = sbase + A_TILE_BYTES + (uint32_t)(b_r0 * LDB + b_n) * 4u;

    const int nglob = bn * TN + b_n;
    const int bb  = nglob / HW;
    const int rem = nglob - bb * HW;
    const int oh  = rem / WW;
    const int ow  = rem - oh * WW;
    const float* xb = g_xt + (size_t)bb * (CIN * HW) + (oh - 1) * WW + (ow - 1);

    auto fill = [&](int s, int kt) {
        const uint32_t soff = (uint32_t)s * STAGE_BYTES;
        // A: 4 x 16B contiguous (blob already smem-layout + swizzled)
        const float* asrc = a_src0 + (size_t)kt * (COUT * KT);
        cp16(a_dst + soff,      asrc);
        cp16(a_dst + soff + 16, asrc + 4);
        cp16(a_dst + soff + 32, asrc + 8);
        cp16(a_dst + soff + 48, asrc + 12);
        // B: one (kh,kw) per K-tile; 16 ci rows, stride HW
        const int p  = kt >> 2;
        const int kh = (p * 11) >> 5;
        const int kw = p - 3 * kh;
        const int ih = oh + kh - 1;
        const int iw = ow + kw - 1;
        const uint32_t sz = ((unsigned)ih < (unsigned)HH && (unsigned)iw < (unsigned)WW) ? 4u : 0u;
        const int ci0 = ((kt & 3) << 5) + b_r0;
        const float* bsrc = xb + (size_t)ci0 * HW + kh * WW + kw;
#pragma unroll
        for (int e = 0; e < 16; ++e)
            cp4z(b_dst + soff + (uint32_t)(e * LDB * 4), bsrc + (size_t)e * HW, sz);
    };

    // ---- warp/lane compute coordinates ----
    const int wm = wid >> 1, wn = wid & 1;
    const int gr = lane >> 2, qc = lane & 3;
    const int mb = wm * 32, nb = wn * 64;

    // ldmatrix addressing (per-lane constants)
    const int rr   = lane & 7;
    const int gsel = lane >> 4;                       // 0/1 -> k-group select
    const uint32_t aoff0 = (uint32_t)(mb + ((lane >> 3) & 1) * 8 + rr) * 128u;
    const uint32_t aoff1 = aoff0 + 16u * 128u;

    float acc[2][8][4];
#pragma unroll
    for (int i = 0; i < 2; ++i)
#pragma unroll
        for (int j = 0; j < 8; ++j)
#pragma unroll
            for (int q = 0; q < 4; ++q) acc[i][j][q] = 0.0f;

    // ---- pipeline prologue ----
    fill(0, 0); cp_commit();
    fill(1, 1); cp_commit();

    int stage = 0;
    for (int kt = 0; kt < NKT; ++kt) {
        cp_wait<1>();
        __syncthreads();

        if (kt + 2 < NKT) {
            int s2 = stage + 2; if (s2 >= NSTAGE) s2 -= NSTAGE;
            fill(s2, kt + 2);
        }
        cp_commit();

        const uint32_t sA = sbase + (uint32_t)stage * STAGE_BYTES;
        const float* Bc = sm + stage * ((A_TILE_FLOATS + B_TILE_FLOATS)) + A_TILE_FLOATS;

#pragma unroll
        for (int s = 0; s < 4; ++s) {
            const int k0 = s * 8;
            // A fragments via ldmatrix.x4 (swizzled 16B column)
            const uint32_t col = (uint32_t)(((2 * s + gsel) ^ rr) << 4);
            uint32_t afr[2][4];
            ldsm4(afr[0], sA + aoff0 + col);
            ldsm4(afr[1], sA + aoff1 + col);

            const float* Bk0 = Bc + (k0 + qc) * LDB;
            const float* Bk4 = Bc + (k0 + qc + 4) * LDB;
            uint32_t bfr[8][2];
#pragma unroll
            for (int j = 0; j < 8; ++j) {
                int n0 = nb + j * 8 + gr;
                bfr[j][0] = __float_as_uint(Bk0[n0]);
                bfr[j][1] = __float_as_uint(Bk4[n0]);
            }
#pragma unroll
            for (int i = 0; i < 2; ++i)
#pragma unroll
                for (int j = 0; j < 8; ++j)
                    mma_tf32(acc[i][j], afr[i], bfr[j]);
        }
        __syncthreads();
        if (++stage == NSTAGE) stage = 0;
    }

    // ---- epilogue: bias + float2 stores ----
#pragma unroll
    for (int i = 0; i < 2; ++i) {
        const int co0 = bm * TM + mb + i * 16 + gr;
        const int co1 = co0 + 8;
        const float bi0 = __ldg(&bias[co0]);
        const float bi1 = __ldg(&bias[co1]);
#pragma unroll
        for (int j = 0; j < 8; ++j) {
            const int n0 = bn * TN + nb + j * 8 + 2 * qc;
            const int b2 = n0 / HW;
            const int r2 = n0 - b2 * HW;
            float* obase = out + (size_t)b2 * (COUT * HW) + r2;
            float2 v0 = make_float2(acc[i][j][0] + bi0, acc[i][j][1] + bi0);
            float2 v1 = make_float2(acc[i][j][2] + bi1, acc[i][j][3] + bi1);
            *reinterpret_cast<float2*>(obase + (size_t)co0 * HW) = v0;
            *reinterpret_cast<float2*>(obase + (size_t)co1 * HW) = v1;
        }
    }
}

extern "C" void kernel_launch(void* const* d_in, const int* in_sizes, int n_in,
                              void* d_out, int out_size) {
    const float* x    = (const float*)d_in[0];  // [32,128,56,56]
    const float* w    = (const float*)d_in[1];  // [256,128,3,3]
    const float* bias = (const float*)d_in[2];  // [256]
    float* out        = (float*)d_out;          // [32,256,56,56]

    cvt_x_kernel<<<(BATCH * CIN * HW / 4 + 255) / 256, 256>>>(x);
    repack_w_kernel<<<(KDIM * COUT) / 256, 256>>>(w);

    cudaFuncSetAttribute(conv_mma_kernel, cudaFuncAttributeMaxDynamicSharedMemorySize,
                         (int)SMEM_TOTAL);
    dim3 grid(NDIM / TN, COUT / TM);  // (784, 2)
    conv_mma_kernel<<<grid, 256, SMEM_TOTAL>>>(bias, out);
}

// round 8
// speedup vs baseline: 6.8110x; 1.8687x over previous
#include <cuda_runtime.h>
#include <cuda_fp16.h>
#include <cstdint>

// Conv2d 3x3 (B=32,Cin=128,56x56 -> Cout=256, pad 1) as implicit GEMM using
// mma.sync.m16n8k16 fp16 (fp32 accum). fp16 and tf32 share 10 mantissa bits
// => same accuracy class as the passing tf32 kernel, 2x the MAC rate.
//
// - x pre-passed to padded channels-last fp16: g_xh[b][ih+1][iw+1][ci]
//   (58x58 zero border) => B tile = k-contiguous 64B runs, unconditional cp16.
// - weights pre-packed per (kt,bm) into exact smem layout (pair-packed rows,
//   XOR-16B swizzle) => A fill = contiguous cp16 copy, ldmatrix conflict-free.
// - A via ldmatrix.x4, B via ldmatrix.x2, 4-stage cp.async pipeline.

namespace {
constexpr int HH = 56, WW = 56, HW = 3136;
constexpr int CIN = 128, COUT = 256, BATCH = 32;
constexpr int KDIM = CIN * 9;           // 1152
constexpr int NDIM = BATCH * HW;        // 100352
constexpr int TM = 128, TN = 128, KT = 32;
constexpr int NKT = KDIM / KT;          // 36
constexpr int NSTAGE = 4;

constexpr int PW = 58;                  // padded H/W
constexpr uint32_t A_TILE_BYTES = TM * KT * 2;          // 8192
constexpr uint32_t B_TILE_BYTES = TN * KT * 2;          // 8192
constexpr uint32_t STAGE_BYTES  = A_TILE_BYTES + B_TILE_BYTES;  // 16384
constexpr uint32_t SMEM_TOTAL   = NSTAGE * STAGE_BYTES;         // 65536
}

__device__ __half g_xh[(size_t)BATCH * PW * PW * CIN];        // padded CL fp16
__device__ __half g_wh[(size_t)NKT * 2 * TM * KT];            // smem-layout blobs

// ---------------- helpers ----------------
__device__ __forceinline__ uint32_t smem_u32(const void* p) {
    uint32_t a;
    asm("{ .reg .u64 t; cvta.to.shared.u64 t, %1; cvt.u32.u64 %0, t; }" : "=r"(a) : "l"(p));
    return a;
}
__device__ __forceinline__ void cp16(uint32_t dst, const void* src) {
    asm volatile("cp.async.cg.shared.global [%0], [%1], 16;"
                 :: "r"(dst), "l"(src) : "memory");
}
__device__ __forceinline__ void cp_commit() {
    asm volatile("cp.async.commit_group;" ::: "memory");
}
template <int N>
__device__ __forceinline__ void cp_wait() {
    asm volatile("cp.async.wait_group %0;" :: "n"(N) : "memory");
}
__device__ __forceinline__ void ldsm4(uint32_t* r, uint32_t addr) {
    asm volatile("ldmatrix.sync.aligned.m8n8.x4.shared.b16 {%0,%1,%2,%3}, [%4];"
                 : "=r"(r[0]), "=r"(r[1]), "=r"(r[2]), "=r"(r[3]) : "r"(addr));
}
__device__ __forceinline__ void ldsm2(uint32_t* r, uint32_t addr) {
    asm volatile("ldmatrix.sync.aligned.m8n8.x2.shared.b16 {%0,%1}, [%2];"
                 : "=r"(r[0]), "=r"(r[1]) : "r"(addr));
}
__device__ __forceinline__ void mma_f16(float* d, const uint32_t* a, const uint32_t* b) {
    asm volatile(
        "mma.sync.aligned.m16n8k16.row.col.f32.f16.f16.f32 "
        "{%0,%1,%2,%3}, {%4,%5,%6,%7}, {%8,%9}, {%0,%1,%2,%3};"
        : "+f"(d[0]), "+f"(d[1]), "+f"(d[2]), "+f"(d[3])
        : "r"(a[0]), "r"(a[1]), "r"(a[2]), "r"(a[3]), "r"(b[0]), "r"(b[1]));
}

// ---------------- pre-pass kernels ----------------
// NCHW fp32 -> padded channels-last fp16, transposed through smem.
__global__ void xpose_kernel(const float* __restrict__ x) {
    __shared__ float tile[CIN][WW + 1];
    const int ih = blockIdx.x;      // 0..55
    const int b  = blockIdx.y;      // 0..31
    const int t  = threadIdx.x;     // 0..255
    const float* src = x + ((size_t)b * CIN * HH + ih) * WW;  // + ci*HW
#pragma unroll
    for (int it = 0; it < CIN * WW / 256; ++it) {
        int flat = it * 256 + t;
        int ci = flat / WW, iw = flat - ci * WW;
        tile[ci][iw] = src[(size_t)ci * HW + iw];
    }
    __syncthreads();
    __half* dst = g_xh + (((size_t)b * PW + (ih + 1)) * PW + 1) * CIN;
#pragma unroll
    for (int it = 0; it < WW * CIN / 256; ++it) {
        int flat = it * 256 + t;
        int iw = flat >> 7, ci = flat & 127;
        dst[(size_t)iw * CIN + ci] = __float2half_rn(tile[ci][iw]);
    }
}

// zero the padded border (rows/cols 0 and 57)
__global__ void border_kernel() {
    int id = blockIdx.x * blockDim.x + threadIdx.x;   // 0 .. 32*58*58-1
    if (id >= BATCH * PW * PW) return;
    int b = id / (PW * PW);
    int r = id - b * (PW * PW);
    int ih = r / PW, iw = r - ih * PW;
    if (ih == 0 || ih == PW - 1 || iw == 0 || iw == PW - 1) {
        float4* p = reinterpret_cast<float4*>(g_xh + (size_t)id * CIN);
#pragma unroll
        for (int q = 0; q < CIN * 2 / 16; ++q) p[q] = make_float4(0.f, 0.f, 0.f, 0.f);
    }
}

// weights -> per-(kt,bm) blobs in exact smem physical layout.
// phys: half off in tile: group=off>>3 (16B), e=off&7; pair=group>>3, sub=group&7;
//       half_co=sub>>2, gs=sub&3; g=gs^(pair&3); co_l=pair*2+half_co; k_l=g*8+e.
__global__ void repack_w_kernel(const float* __restrict__ w) {
    int id = blockIdx.x * blockDim.x + threadIdx.x;   // 0 .. NKT*2*4096-1
    int off  = id & 4095;
    int tilе = id >> 12;
    int bm = tilе & 1, kt = tilе >> 1;
    int group = off >> 3, e = off & 7;
    int pair = group >> 3, sub = group & 7;
    int hco = sub >> 2, gs = sub & 3;
    int g = gs ^ (pair & 3);
    int co = bm * TM + pair * 2 + hco;
    int k_l = g * 8 + e;
    int p  = kt >> 2;
    int ci = ((kt & 3) << 5) + k_l;
    g_wh[id] = __float2half_rn(w[(size_t)co * KDIM + ci * 9 + p]);
}

// ---------------- main kernel ----------------
__global__ __launch_bounds__(256, 2)
void conv_mma_kernel(const float* __restrict__ bias, float* __restrict__ out)
{
    extern __shared__ char smc[];
    const uint32_t sbase = smem_u32(smc);

    const int tid  = threadIdx.x;
    const int lane = tid & 31;
    const int wid  = tid >> 5;
    const int bn   = blockIdx.x;   // 0..783
    const int bm   = blockIdx.y;   // 0..1

    // ---- fill assignments ----
    // A: contiguous 32B per thread from blob
    const __half* a_src0 = g_wh + (size_t)bm * (TM * KT) + tid * 16;
    const uint32_t a_dst = (uint32_t)tid * 32u;
    // B: thread -> n column (2 threads/n), two 16B k-groups
    const int b_n  = tid >> 1;
    const int gsel = (tid & 1) * 2;
    const int nglob = bn * TN + b_n;
    const int bb  = nglob / HW;
    const int rem = nglob - bb * HW;
    const int oh  = rem / WW;
    const int ow  = rem - oh * WW;
    const __half* xb = g_xh + ((size_t)bb * PW + oh) * (PW * CIN) + (size_t)ow * CIN;
    const int pairB = b_n >> 1, halfB = b_n & 1;
    const uint32_t bg0 = (uint32_t)(pairB * 8 + halfB * 4 + (gsel       ^ (pairB & 3)));
    const uint32_t bg1 = (uint32_t)(pairB * 8 + halfB * 4 + ((gsel + 1) ^ (pairB & 3)));

    auto fill = [&](int s, int kt) {
        const uint32_t soff = (uint32_t)s * STAGE_BYTES;
        const __half* asrc = a_src0 + (size_t)kt * (2 * TM * KT);
        cp16(sbase + soff + a_dst,       asrc);
        cp16(sbase + soff + a_dst + 16,  asrc + 8);
        const int p  = kt >> 2;
        const int kh = (p * 11) >> 5;
        const int kw = p - 3 * kh;
        const int ci0 = ((kt & 3) << 5) + gsel * 8;
        const __half* bsrc = xb + ((size_t)kh * PW + kw) * CIN + ci0;
        const uint32_t bb0 = sbase + soff + A_TILE_BYTES;
        cp16(bb0 + bg0 * 16u, bsrc);
        cp16(bb0 + bg1 * 16u, bsrc + 8);
    };

    // ---- warp/lane compute coordinates ----
    const int wm = wid >> 1, wn = wid & 1;
    const int gr = lane >> 2, qc = lane & 3;
    const int mb = wm * 32, nb = wn * 64;

    // ldmatrix per-lane constants
    const int mrow = (lane & 7) + (((lane >> 3) & 1) << 3);   // row within m16
    const int matk = lane >> 4;                                // 0/1 k-half
    // A: per i block
    uint32_t aoffbase[2], apx[2];
#pragma unroll
    for (int i = 0; i < 2; ++i) {
        int co_l = mb + i * 16 + mrow;
        int pa = co_l >> 1, ha = co_l & 1;
        aoffbase[i] = (uint32_t)(pa * 8 + ha * 4) * 16u;
        apx[i] = (uint32_t)(pa & 3);
    }
    // B: per j octet (lanes 0..15 meaningful; others mirror)
    const int rB = lane & 7;
    const int matB = (lane >> 3) & 1;
    uint32_t boffbase[8], bpx[8];
#pragma unroll
    for (int j = 0; j < 8; ++j) {
        int n_l = nb + j * 8 + rB;
        int pb = n_l >> 1, hb = n_l & 1;
        boffbase[j] = (uint32_t)(pb * 8 + hb * 4) * 16u;
        bpx[j] = (uint32_t)(pb & 3);
    }

    float acc[2][8][4];
#pragma unroll
    for (int i = 0; i < 2; ++i)
#pragma unroll
        for (int j = 0; j < 8; ++j)
#pragma unroll
            for (int q = 0; q < 4; ++q) acc[i][j][q] = 0.0f;

    // ---- pipeline prologue (depth 3 of 4 stages) ----
    fill(0, 0); cp_commit();
    fill(1, 1); cp_commit();
    fill(2, 2); cp_commit();

    int stage = 0;
    for (int kt = 0; kt < NKT; ++kt) {
        cp_wait<2>();
        __syncthreads();

        if (kt + 3 < NKT) {
            int s3 = stage + 3; if (s3 >= NSTAGE) s3 -= NSTAGE;
            fill(s3, kt + 3);
        }
        cp_commit();

        const uint32_t sA = sbase + (uint32_t)stage * STAGE_BYTES;
        const uint32_t sB = sA + A_TILE_BYTES;

#pragma unroll
        for (int ks = 0; ks < 2; ++ks) {
            uint32_t afr[2][4];
#pragma unroll
            for (int i = 0; i < 2; ++i) {
                uint32_t g = (uint32_t)(ks * 2 + matk);
                ldsm4(afr[i], sA + aoffbase[i] + ((g ^ apx[i]) << 4));
            }
            uint32_t bfr[8][2];
#pragma unroll
            for (int j = 0; j < 8; ++j) {
                uint32_t g = (uint32_t)(ks * 2 + matB);
                ldsm2(bfr[j], sB + boffbase[j] + ((g ^ bpx[j]) << 4));
            }
#pragma unroll
            for (int i = 0; i < 2; ++i)
#pragma unroll
                for (int j = 0; j < 8; ++j)
                    mma_f16(acc[i][j], afr[i], bfr[j]);
        }
        __syncthreads();
        if (++stage == NSTAGE) stage = 0;
    }

    // ---- epilogue: bias + float2 stores ----
#pragma unroll
    for (int i = 0; i < 2; ++i) {
        const int co0 = bm * TM + mb + i * 16 + gr;
        const int co1 = co0 + 8;
        const float bi0 = __ldg(&bias[co0]);
        const float bi1 = __ldg(&bias[co1]);
#pragma unroll
        for (int j = 0; j < 8; ++j) {
            const int n0 = bn * TN + nb + j * 8 + 2 * qc;
            const int b2 = n0 / HW;
            const int r2 = n0 - b2 * HW;
            float* obase = out + (size_t)b2 * (COUT * HW) + r2;
            float2 v0 = make_float2(acc[i][j][0] + bi0, acc[i][j][1] + bi0);
            float2 v1 = make_float2(acc[i][j][2] + bi1, acc[i][j][3] + bi1);
            *reinterpret_cast<float2*>(obase + (size_t)co0 * HW) = v0;
            *reinterpret_cast<float2*>(obase + (size_t)co1 * HW) = v1;
        }
    }
}

extern "C" void kernel_launch(void* const* d_in, const int* in_sizes, int n_in,
                              void* d_out, int out_size) {
    const float* x    = (const float*)d_in[0];  // [32,128,56,56]
    const float* w    = (const float*)d_in[1];  // [256,128,3,3]
    const float* bias = (const float*)d_in[2];  // [256]
    float* out        = (float*)d_out;          // [32,256,56,56]

    border_kernel<<<(BATCH * PW * PW + 255) / 256, 256>>>();
    {
        dim3 g(HH, BATCH);
        xpose_kernel<<<g, 256>>>(x);
    }
    repack_w_kernel<<<(NKT * 2 * TM * KT) / 256, 256>>>(w);

    cudaFuncSetAttribute(conv_mma_kernel, cudaFuncAttributeMaxDynamicSharedMemorySize,
                         (int)SMEM_TOTAL);
    dim3 grid(NDIM / TN, COUT / TM);  // (784, 2)
    conv_mma_kernel<<<grid, 256, SMEM_TOTAL>>>(bias, out);
}

// round 9
// speedup vs baseline: 8.4605x; 1.2422x over previous
#include <cuda_runtime.h>
#include <cuda_fp16.h>
#include <cstdint>

// Conv2d 3x3 (B=32,Cin=128,56x56 -> Cout=256, pad 1) as implicit GEMM using
// mma.sync.m16n8k16 fp16 (fp32 accum).
//
// R9: one __syncthreads per K-tile (canonical wait->sync->fill->compute),
//     B fragments via paired ldmatrix.x4 (8 instead of 16 LDSM/warp/K-tile),
//     stage = kt&3 with unroll-4 so stage math constant-folds.

namespace {
constexpr int HH = 56, WW = 56, HW = 3136;
constexpr int CIN = 128, COUT = 256, BATCH = 32;
constexpr int KDIM = CIN * 9;           // 1152
constexpr int NDIM = BATCH * HW;        // 100352
constexpr int TM = 128, TN = 128, KT = 32;
constexpr int NKT = KDIM / KT;          // 36
constexpr int NSTAGE = 4;

constexpr int PW = 58;                  // padded H/W
constexpr uint32_t A_TILE_BYTES = TM * KT * 2;          // 8192
constexpr uint32_t B_TILE_BYTES = TN * KT * 2;          // 8192
constexpr uint32_t STAGE_BYTES  = A_TILE_BYTES + B_TILE_BYTES;  // 16384
constexpr uint32_t SMEM_TOTAL   = NSTAGE * STAGE_BYTES;         // 65536
}

__device__ __half g_xh[(size_t)BATCH * PW * PW * CIN];        // padded CL fp16
__device__ __half g_wh[(size_t)NKT * 2 * TM * KT];            // smem-layout blobs

// ---------------- helpers ----------------
__device__ __forceinline__ uint32_t smem_u32(const void* p) {
    uint32_t a;
    asm("{ .reg .u64 t; cvta.to.shared.u64 t, %1; cvt.u32.u64 %0, t; }" : "=r"(a) : "l"(p));
    return a;
}
__device__ __forceinline__ void cp16(uint32_t dst, const void* src) {
    asm volatile("cp.async.cg.shared.global [%0], [%1], 16;"
                 :: "r"(dst), "l"(src) : "memory");
}
__device__ __forceinline__ void cp_commit() {
    asm volatile("cp.async.commit_group;" ::: "memory");
}
template <int N>
__device__ __forceinline__ void cp_wait() {
    asm volatile("cp.async.wait_group %0;" :: "n"(N) : "memory");
}
__device__ __forceinline__ void ldsm4(uint32_t* r, uint32_t addr) {
    asm volatile("ldmatrix.sync.aligned.m8n8.x4.shared.b16 {%0,%1,%2,%3}, [%4];"
                 : "=r"(r[0]), "=r"(r[1]), "=r"(r[2]), "=r"(r[3]) : "r"(addr));
}
__device__ __forceinline__ void mma_f16(float* d, const uint32_t* a, const uint32_t* b) {
    asm volatile(
        "mma.sync.aligned.m16n8k16.row.col.f32.f16.f16.f32 "
        "{%0,%1,%2,%3}, {%4,%5,%6,%7}, {%8,%9}, {%0,%1,%2,%3};"
        : "+f"(d[0]), "+f"(d[1]), "+f"(d[2]), "+f"(d[3])
        : "r"(a[0]), "r"(a[1]), "r"(a[2]), "r"(a[3]), "r"(b[0]), "r"(b[1]));
}

// ---------------- pre-pass kernels ----------------
__global__ void xpose_kernel(const float* __restrict__ x) {
    __shared__ float tile[CIN][WW + 1];
    const int ih = blockIdx.x;
    const int b  = blockIdx.y;
    const int t  = threadIdx.x;
    const float* src = x + ((size_t)b * CIN * HH + ih) * WW;
#pragma unroll
    for (int it = 0; it < CIN * WW / 256; ++it) {
        int flat = it * 256 + t;
        int ci = flat / WW, iw = flat - ci * WW;
        tile[ci][iw] = src[(size_t)ci * HW + iw];
    }
    __syncthreads();
    __half* dst = g_xh + (((size_t)b * PW + (ih + 1)) * PW + 1) * CIN;
#pragma unroll
    for (int it = 0; it < WW * CIN / 256; ++it) {
        int flat = it * 256 + t;
        int iw = flat >> 7, ci = flat & 127;
        dst[(size_t)iw * CIN + ci] = __float2half_rn(tile[ci][iw]);
    }
}

__global__ void border_kernel() {
    int id = blockIdx.x * blockDim.x + threadIdx.x;
    if (id >= BATCH * PW * PW) return;
    int b = id / (PW * PW);
    int r = id - b * (PW * PW);
    int ih = r / PW, iw = r - ih * PW;
    if (ih == 0 || ih == PW - 1 || iw == 0 || iw == PW - 1) {
        float4* p = reinterpret_cast<float4*>(g_xh + (size_t)id * CIN);
#pragma unroll
        for (int q = 0; q < CIN * 2 / 16; ++q) p[q] = make_float4(0.f, 0.f, 0.f, 0.f);
    }
}

// weights -> per-(kt,bm) blobs in exact smem physical layout (same as R8).
__global__ void repack_w_kernel(const float* __restrict__ w) {
    int id = blockIdx.x * blockDim.x + threadIdx.x;
    int off  = id & 4095;
    int tile = id >> 12;
    int bm = tile & 1, kt = tile >> 1;
    int group = off >> 3, e = off & 7;
    int pair = group >> 3, sub = group & 7;
    int hco = sub >> 2, gs = sub & 3;
    int g = gs ^ (pair & 3);
    int co = bm * TM + pair * 2 + hco;
    int k_l = g * 8 + e;
    int p  = kt >> 2;
    int ci = ((kt & 3) << 5) + k_l;
    g_wh[id] = __float2half_rn(w[(size_t)co * KDIM + ci * 9 + p]);
}

// ---------------- main kernel ----------------
__global__ __launch_bounds__(256, 2)
void conv_mma_kernel(const float* __restrict__ bias, float* __restrict__ out)
{
    extern __shared__ char smc[];
    const uint32_t sbase = smem_u32(smc);

    const int tid  = threadIdx.x;
    const int lane = tid & 31;
    const int wid  = tid >> 5;
    const int bn   = blockIdx.x;
    const int bm   = blockIdx.y;

    // ---- fill assignments ----
    const __half* a_src0 = g_wh + (size_t)bm * (TM * KT) + tid * 16;
    const uint32_t a_dst = (uint32_t)tid * 32u;

    const int b_n  = tid >> 1;
    const int gsel = (tid & 1) * 2;
    const int nglob = bn * TN + b_n;
    const int bb  = nglob / HW;
    const int rem = nglob - bb * HW;
    const int oh  = rem / WW;
    const int ow  = rem - oh * WW;
    const __half* xb = g_xh + ((size_t)bb * PW + oh) * (PW * CIN) + (size_t)ow * CIN;
    const int pairB = b_n >> 1, halfB = b_n & 1;
    const uint32_t bg0 = (uint32_t)(pairB * 8 + halfB * 4 + (gsel       ^ (pairB & 3)));
    const uint32_t bg1 = (uint32_t)(pairB * 8 + halfB * 4 + ((gsel + 1) ^ (pairB & 3)));

    auto fill = [&](int s, int kt) {
        const uint32_t soff = (uint32_t)s * STAGE_BYTES;
        const __half* asrc = a_src0 + (size_t)kt * (2 * TM * KT);
        cp16(sbase + soff + a_dst,       asrc);
        cp16(sbase + soff + a_dst + 16,  asrc + 8);
        const int p  = kt >> 2;
        const int kh = (p * 11) >> 5;
        const int kw = p - 3 * kh;
        const int ci0 = ((kt & 3) << 5) + gsel * 8;
        const __half* bsrc = xb + ((size_t)kh * PW + kw) * CIN + ci0;
        const uint32_t bb0 = sbase + soff + A_TILE_BYTES;
        cp16(bb0 + bg0 * 16u, bsrc);
        cp16(bb0 + bg1 * 16u, bsrc + 8);
    };

    // ---- warp/lane compute coordinates ----
    const int wm = wid >> 1, wn = wid & 1;
    const int gr = lane >> 2, qc = lane & 3;
    const int mb = wm * 32, nb = wn * 64;

    // A ldmatrix constants (x4: lanes 0-15 matrices 0/1 = m16 rows; 16-31 = k-half)
    const int mrow = (lane & 7) + (((lane >> 3) & 1) << 3);
    const int matk = lane >> 4;
    uint32_t aoffbase[2], apx[2];
#pragma unroll
    for (int i = 0; i < 2; ++i) {
        int co_l = mb + i * 16 + mrow;
        int pa = co_l >> 1, ha = co_l & 1;
        aoffbase[i] = (uint32_t)(pa * 8 + ha * 4) * 16u;
        apx[i] = (uint32_t)(pa & 3);
    }

    // B paired-x4 constants: lane group q=lane>>3 -> (octet q>>1, k-half q&1)
    const int rB = lane & 7;
    const uint32_t hB = (lane >> 3) & 1;          // k-half for this lane's matrix
    const int qoct = lane >> 4;                   // 0/1: first or second octet of pair
    uint32_t bBase[4], bPx[4];
#pragma unroll
    for (int pj = 0; pj < 4; ++pj) {
        int j = 2 * pj + qoct;
        int n_l = nb + j * 8 + rB;
        int pb = n_l >> 1, hb = n_l & 1;
        bBase[pj] = (uint32_t)(pb * 8 + hb * 4) * 16u;
        bPx[pj] = (uint32_t)(pb & 3);
    }

    float acc[2][8][4];
#pragma unroll
    for (int i = 0; i < 2; ++i)
#pragma unroll
        for (int j = 0; j < 8; ++j)
#pragma unroll
            for (int q = 0; q < 4; ++q) acc[i][j][q] = 0.0f;

    // ---- pipeline prologue (depth 3 of 4 stages) ----
    fill(0, 0); cp_commit();
    fill(1, 1); cp_commit();
    fill(2, 2); cp_commit();

#pragma unroll 4
    for (int kt = 0; kt < NKT; ++kt) {
        cp_wait<2>();
        __syncthreads();   // single barrier: prev compute done + stage kt visible

        if (kt + 3 < NKT) fill((kt + 3) & 3, kt + 3);
        cp_commit();

        const uint32_t sA = sbase + (uint32_t)(kt & 3) * STAGE_BYTES;
        const uint32_t sB = sA + A_TILE_BYTES;

#pragma unroll
        for (int ks = 0; ks < 2; ++ks) {
            uint32_t afr[2][4];
#pragma unroll
            for (int i = 0; i < 2; ++i) {
                uint32_t g = (uint32_t)(ks * 2 + matk);
                ldsm4(afr[i], sA + aoffbase[i] + ((g ^ apx[i]) << 4));
            }
            uint32_t bfr[4][4];
#pragma unroll
            for (int pj = 0; pj < 4; ++pj) {
                uint32_t g = (uint32_t)(ks * 2) + hB;
                ldsm4(bfr[pj], sB + bBase[pj] + ((g ^ bPx[pj]) << 4));
            }
#pragma unroll
            for (int i = 0; i < 2; ++i)
#pragma unroll
                for (int j = 0; j < 8; ++j)
                    mma_f16(acc[i][j], afr[i], &bfr[j >> 1][(j & 1) * 2]);
        }
    }

    // ---- epilogue: bias + float2 stores ----
    __syncthreads();
#pragma unroll
    for (int i = 0; i < 2; ++i) {
        const int co0 = bm * TM + mb + i * 16 + gr;
        const int co1 = co0 + 8;
        const float bi0 = __ldg(&bias[co0]);
        const float bi1 = __ldg(&bias[co1]);
#pragma unroll
        for (int j = 0; j < 8; ++j) {
            const int n0 = bn * TN + nb + j * 8 + 2 * qc;
            const int b2 = n0 / HW;
            const int r2 = n0 - b2 * HW;
            float* obase = out + (size_t)b2 * (COUT * HW) + r2;
            float2 v0 = make_float2(acc[i][j][0] + bi0, acc[i][j][1] + bi0);
            float2 v1 = make_float2(acc[i][j][2] + bi1, acc[i][j][3] + bi1);
            *reinterpret_cast<float2*>(obase + (size_t)co0 * HW) = v0;
            *reinterpret_cast<float2*>(obase + (size_t)co1 * HW) = v1;
        }
    }
}

extern "C" void kernel_launch(void* const* d_in, const int* in_sizes, int n_in,
                              void* d_out, int out_size) {
    const float* x    = (const float*)d_in[0];  // [32,128,56,56]
    const float* w    = (const float*)d_in[1];  // [256,128,3,3]
    const float* bias = (const float*)d_in[2];  // [256]
    float* out        = (float*)d_out;          // [32,256,56,56]

    border_kernel<<<(BATCH * PW * PW + 255) / 256, 256>>>();
    {
        dim3 g(HH, BATCH);
        xpose_kernel<<<g, 256>>>(x);
    }
    repack_w_kernel<<<(NKT * 2 * TM * KT) / 256, 256>>>(w);

    cudaFuncSetAttribute(conv_mma_kernel, cudaFuncAttributeMaxDynamicSharedMemorySize,
                         (int)SMEM_TOTAL);
    dim3 grid(NDIM / TN, COUT / TM);  // (784, 2)
    conv_mma_kernel<<<grid, 256, SMEM_TOTAL>>>(bias, out);
}